// round 14
// baseline (speedup 1.0000x reference)
#include <cuda_runtime.h>
#include <math.h>

#define B_SZ 64
#define S_SZ 1024
#define I_SZ 512
#define H_SZ 512

// ---------------- static device scratch (no allocations allowed) ----------------
__device__ float g_xg  [(size_t)S_SZ * 3 * B_SZ * H_SZ];  // [S][3][B][H]
__device__ float g_ys0 [(size_t)S_SZ * B_SZ * H_SZ];      // layer-0 fwd outputs [S][B][H]
__device__ float g_ys1 [(size_t)S_SZ * B_SZ * H_SZ];      // layer-1 fwd outputs
__device__ float g_hb0 [B_SZ * H_SZ];
__device__ float g_hb1 [B_SZ * H_SZ];
__device__ float g_wpk0[3 * 512 * 512];                   // packed Wh layer0 (fallback path)
__device__ float g_wpk1[3 * 512 * 512];                   // packed Wh layer1 (fallback path)
__device__ float g_wf0 [3 * 512 * 512];                   // frag-packed Wh layer0 (tensor path)
__device__ float g_wf1 [3 * 512 * 512];                   // frag-packed Wh layer1 (tensor path)

// ---------------- tf32 helpers ----------------
__device__ __forceinline__ unsigned f2tf(float x) {
    unsigned u;
    asm("cvt.rna.tf32.f32 %0, %1;" : "=r"(u) : "f"(x));
    return u;
}

__device__ __forceinline__ void mma8(float* c, const unsigned* a, unsigned b0, unsigned b1) {
    asm volatile(
        "mma.sync.aligned.m16n8k8.row.col.f32.tf32.tf32.f32 "
        "{%0,%1,%2,%3}, {%4,%5,%6,%7}, {%8,%9}, {%0,%1,%2,%3};"
        : "+f"(c[0]), "+f"(c[1]), "+f"(c[2]), "+f"(c[3])
        : "r"(a[0]), "r"(a[1]), "r"(a[2]), "r"(a[3]), "r"(b0), "r"(b1));
}

// ---------------- projection GEMM (round-13 verified, pipelined) ----------------
__global__ void __launch_bounds__(256) proj_kernel(
    const float* __restrict__ X, long sb, long ss,
    const float* __restrict__ W, const float* __restrict__ bias,
    float* __restrict__ out, int Srows)
{
    __shared__ float As[128][36];
    __shared__ float Bs[32][136];

    const int M  = Srows * B_SZ;
    const int m0 = blockIdx.y * 128;
    const int n0 = blockIdx.x * 128;
    const int g  = n0 >> 9;
    const int h0 = n0 & 511;
    const float* Wg = W + (size_t)g * H_SZ * H_SZ;

    const int tid  = threadIdx.x;
    const int lane = tid & 31;
    const int warp = tid >> 5;
    const int wm   = warp & 3;
    const int wn   = warp >> 2;

    float acc[2][8][4];
#pragma unroll
    for (int i = 0; i < 2; i++)
#pragma unroll
        for (int jf = 0; jf < 8; jf++)
#pragma unroll
            for (int k = 0; k < 4; k++) acc[i][jf][k] = 0.f;

    float4 av[4], bv[4];

#pragma unroll
    for (int i = 0; i < 4; i++) {
        int idx = tid + i * 256;
        int row = idx >> 3;
        int kk  = (idx & 7) << 2;
        av[i] = make_float4(0.f, 0.f, 0.f, 0.f);
        int r = m0 + row;
        if (r < M) {
            int s = r >> 6, b = r & 63;
            av[i] = *(const float4*)(X + (size_t)b * sb + (size_t)s * ss + kk);
        }
        int kkb = idx >> 5;
        int nn  = (idx & 31) << 2;
        bv[i] = *(const float4*)(Wg + (size_t)kkb * H_SZ + h0 + nn);
    }

    for (int k0 = 0; k0 < H_SZ; k0 += 32) {
#pragma unroll
        for (int i = 0; i < 4; i++) {
            int idx = tid + i * 256;
            int row = idx >> 3;
            int kk  = (idx & 7) << 2;
            As[row][kk + 0] = __uint_as_float(f2tf(av[i].x));
            As[row][kk + 1] = __uint_as_float(f2tf(av[i].y));
            As[row][kk + 2] = __uint_as_float(f2tf(av[i].z));
            As[row][kk + 3] = __uint_as_float(f2tf(av[i].w));
            int kkb = idx >> 5;
            int nn  = (idx & 31) << 2;
            Bs[kkb][nn + 0] = __uint_as_float(f2tf(bv[i].x));
            Bs[kkb][nn + 1] = __uint_as_float(f2tf(bv[i].y));
            Bs[kkb][nn + 2] = __uint_as_float(f2tf(bv[i].z));
            Bs[kkb][nn + 3] = __uint_as_float(f2tf(bv[i].w));
        }
        __syncthreads();

        if (k0 + 32 < H_SZ) {
            const int kn = k0 + 32;
#pragma unroll
            for (int i = 0; i < 4; i++) {
                int idx = tid + i * 256;
                int row = idx >> 3;
                int kk  = (idx & 7) << 2;
                av[i] = make_float4(0.f, 0.f, 0.f, 0.f);
                int r = m0 + row;
                if (r < M) {
                    int s = r >> 6, b = r & 63;
                    av[i] = *(const float4*)(X + (size_t)b * sb + (size_t)s * ss + kn + kk);
                }
                int kkb = idx >> 5;
                int nn  = (idx & 31) << 2;
                bv[i] = *(const float4*)(Wg + (size_t)(kn + kkb) * H_SZ + h0 + nn);
            }
        }

#pragma unroll
        for (int kq = 0; kq < 4; kq++) {
            const int kr = kq * 8;
            unsigned a[2][4];
#pragma unroll
            for (int mf = 0; mf < 2; mf++) {
                int rb = wm * 32 + mf * 16 + (lane >> 2);
                int c  = kr + (lane & 3);
                a[mf][0] = __float_as_uint(As[rb][c]);
                a[mf][1] = __float_as_uint(As[rb + 8][c]);
                a[mf][2] = __float_as_uint(As[rb][c + 4]);
                a[mf][3] = __float_as_uint(As[rb + 8][c + 4]);
            }
#pragma unroll
            for (int nf = 0; nf < 8; nf++) {
                int cb = wn * 64 + nf * 8 + (lane >> 2);
                unsigned b0 = __float_as_uint(Bs[kr + (lane & 3)][cb]);
                unsigned b1 = __float_as_uint(Bs[kr + (lane & 3) + 4][cb]);
                mma8(acc[0][nf], a[0], b0, b1);
                mma8(acc[1][nf], a[1], b0, b1);
            }
        }
        __syncthreads();
    }

#pragma unroll
    for (int mf = 0; mf < 2; mf++) {
#pragma unroll
        for (int nf = 0; nf < 8; nf++) {
            int col = wn * 64 + nf * 8 + ((lane & 3) << 1);
            int h   = h0 + col;
            float b0v = bias[g * H_SZ + h];
            float b1v = bias[g * H_SZ + h + 1];
            int r = m0 + wm * 32 + mf * 16 + (lane >> 2);
            if (r < M) {
                int s = r >> 6, b = r & 63;
                float* o = out + ((size_t)(s * 3 + g) * B_SZ + b) * H_SZ + h;
                o[0] = acc[mf][nf][0] + b0v;
                o[1] = acc[mf][nf][1] + b1v;
            }
            int r2 = r + 8;
            if (r2 < M) {
                int s = r2 >> 6, b = r2 & 63;
                float* o = out + ((size_t)(s * 3 + g) * B_SZ + b) * H_SZ + h;
                o[0] = acc[mf][nf][2] + b0v;
                o[1] = acc[mf][nf][3] + b1v;
            }
        }
    }
}

// ---------------- Wh pre-pack for fallback scan8 ----------------
__global__ void __launch_bounds__(256) pack_wh(const float* __restrict__ Wh,
                                               float* __restrict__ wpk)
{
    int idx = blockIdx.x * 256 + threadIdx.x;
    if (idx < 3 * 512 * 512) {
        int col = idx & 511;
        int k   = (idx >> 9) & 511;
        int g   = idx >> 18;
        wpk[((((size_t)g * 128 + (k >> 2)) * 512 + col) << 2) + (k & 3)] = Wh[idx];
    }
}

// ---------------- Wh frag-pack for tensor scan (verified round 11) ----------------
#define FRAG_PAIRS 393216
__global__ void __launch_bounds__(256) pack_frag(const float* __restrict__ Wh,
                                                 float* __restrict__ wf)
{
    int p = blockIdx.x * 256 + threadIdx.x;
    if (p < FRAG_PAIRS) {
        int lane = p & 31;
        int kt   = (p >> 5) & 63;
        int nf   = (p >> 11) & 3;
        int cg   = (p >> 13) & 15;
        int g    = p >> 17;
        int col  = cg * 32 + nf * 8 + (lane >> 2);
        int k    = kt * 8 + (lane & 3);
        wf[2 * p + 0] = __uint_as_float(f2tf(Wh[((size_t)g * 512 + k) * 512 + col]));
        wf[2 * p + 1] = __uint_as_float(f2tf(Wh[((size_t)g * 512 + k + 4) * 512 + col]));
    }
}

// ================= PRIMARY scan: tensor mma, cluster-16, zero-staging =================
// Round-14: A-frags loaded directly from global ys via per-lane __ldcg (ys holds
// tf32-pre-rounded h, so inputs are bit-identical to the old smem path). No hs
// buffer, no staging loop, one syncthreads per step. All 3 gates' weights in smem.
#define SM_RED   49152                              // after 3 x 16384-float gate slices
#define S16T_SMEM_FLOATS (SM_RED + 4 * 16 * 100)    // 55552
#define S16T_SMEM_BYTES  (S16T_SMEM_FLOATS * 4)     // 222208 B

__global__ void __launch_bounds__(512, 1)
scan16t_kernel(const float* __restrict__ xg,   // [S][3][B][H]
               const float* __restrict__ wf,   // frag-packed Wh (this layer)
               float* __restrict__ ys,         // [S][B][H] (stores tf32-rounded h)
               int S)
{
    extern __shared__ float sm[];

    const int tid  = threadIdx.x;
    const int lane = tid & 31;
    const int w    = tid >> 5;
    const int kc   = w & 3;           // mma warps: K-slice
    const int g    = w >> 2;          // mma warps: gate (0..2); w>=12 inactive
    const int cg   = blockIdx.x;      // colgroup (32 cols)
    const int j0   = cg << 5;
    const int b0   = blockIdx.y << 4; // 16 batches

    // one-time: ALL 3 gate frag slices into smem (each 16384 floats)
    {
        const float4* src = (const float4*)(wf);
        float4*       dst = (float4*)(sm);
#pragma unroll
        for (int gg = 0; gg < 3; gg++) {
            const float4* s4 = src + (size_t)(gg * 16 + cg) * 4096;
            float4*       d4 = dst + gg * 4096;
            for (int i = tid; i < 4096; i += 512) d4[i] = s4[i];
        }
    }
    // one-time: zero red (so s==0 gate reads zeros)
    for (int i = tid; i < 4 * 16 * 100; i += 512) sm[SM_RED + i] = 0.f;

    const float* wsmg = sm + (g < 3 ? g * 16384 : 0);

    const int gb = tid >> 5;   // gate-stage batch (0..15)
    const int gj = tid & 31;   // gate-stage col   (0..31)

    // mma-warp A-frag row pointers (row = b0 + (lane>>2), partner +8)
    const int rb  = lane >> 2;
    const int kap = lane & 3;

    float hprev = 0.f;

    float x0, x1, x2;
    {
        const size_t xb = ((size_t)(0 * 3 + 0) * B_SZ + b0 + gb) * H_SZ + j0 + gj;
        x0 = __ldg(xg + xb);
        x1 = __ldg(xg + xb + (size_t)B_SZ * H_SZ);
        x2 = __ldg(xg + xb + (size_t)2 * B_SZ * H_SZ);
    }
    __syncthreads();   // weight fills + red zeros visible

    for (int s = 0; s < S; s++) {
        if (w < 12 && s > 0) {
            const float* pr0 = ys + (size_t)(s - 1) * (B_SZ * H_SZ)
                                  + (size_t)(b0 + rb) * H_SZ + kap;
            const float* pr1 = pr0 + 8 * H_SZ;
            const int ktb = kc << 4;

            float c[4][4];
#pragma unroll
            for (int nf = 0; nf < 4; nf++)
#pragma unroll
                for (int q = 0; q < 4; q++) c[nf][q] = 0.f;

#pragma unroll 4
            for (int kt = 0; kt < 16; kt++) {
                const int k0 = (ktb + kt) << 3;
                unsigned ah[4];
                ah[0] = __float_as_uint(__ldcg(pr0 + k0));
                ah[1] = __float_as_uint(__ldcg(pr1 + k0));
                ah[2] = __float_as_uint(__ldcg(pr0 + k0 + 4));
                ah[3] = __float_as_uint(__ldcg(pr1 + k0 + 4));
#pragma unroll
                for (int nf = 0; nf < 4; nf++) {
                    unsigned long long bv = *(const unsigned long long*)
                        (wsmg + nf * 4096 + (ktb + kt) * 64 + lane * 2);
                    mma8(c[nf], ah, (unsigned)bv, (unsigned)(bv >> 32));
                }
            }

#pragma unroll
            for (int nf = 0; nf < 4; nf++) {
                int gcol = (g << 5) + (nf << 3) + ((lane & 3) << 1);
                int row  = lane >> 2;
                float2 p01 = make_float2(c[nf][0], c[nf][1]);
                float2 p23 = make_float2(c[nf][2], c[nf][3]);
                *(float2*)&sm[SM_RED + kc * 1600 + row * 100 + gcol]       = p01;
                *(float2*)&sm[SM_RED + kc * 1600 + (row + 8) * 100 + gcol] = p23;
            }
        }
        __syncthreads();

        // gate stage: 512 threads, one per (batch gb, col gj)
        {
            float s0 = 0.f, s1 = 0.f, s2 = 0.f;
#pragma unroll
            for (int c8 = 0; c8 < 4; c8++) {
                s0 += sm[SM_RED + c8 * 1600 + gb * 100 +      gj];
                s1 += sm[SM_RED + c8 * 1600 + gb * 100 + 32 + gj];
                s2 += sm[SM_RED + c8 * 1600 + gb * 100 + 64 + gj];
            }
            float r  = 1.f / (1.f + expf(-(x0 + s0)));
            float z  = 1.f / (1.f + expf(-(x1 + s1)));
            float n  = tanhf(x2 + r * s2);
            float hn = (1.f - z) * n + z * hprev;
            hprev = hn;
            ys[((size_t)s * B_SZ + b0 + gb) * H_SZ + j0 + gj] = __uint_as_float(f2tf(hn));
        }

        // split cluster barrier; prefetch next xg in the gap
        asm volatile("barrier.cluster.arrive.aligned;" ::: "memory");
        if (s + 1 < S) {
            const size_t xb = ((size_t)((s + 1) * 3 + 0) * B_SZ + b0 + gb) * H_SZ + j0 + gj;
            x0 = __ldg(xg + xb);
            x1 = __ldg(xg + xb + (size_t)B_SZ * H_SZ);
            x2 = __ldg(xg + xb + (size_t)2 * B_SZ * H_SZ);
        }
        asm volatile("barrier.cluster.wait.aligned;" ::: "memory");
    }
}

// ================= FALLBACK scan: exact round-6 kernel (cluster 8) =================
#define SCAN8_SMEM_BYTES ((4096 + 12288) * 4)

__global__ void __launch_bounds__(512, 1) __cluster_dims__(8, 1, 1)
scan8_kernel(const float* __restrict__ xg, const float4* __restrict__ wpk,
             float* __restrict__ ys, int S)
{
    extern __shared__ float sm[];
    float*  hs  = sm;
    float*  red = sm + 4096;
    float4* hs4 = (float4*)hs;

    const int tid  = threadIdx.x;
    const int lane = tid & 31;
    const int w    = tid >> 5;
    const int kc   = w >> 1;
    const int jh   = w & 1;
    const int j0   = blockIdx.x << 6;
    const int b0   = blockIdx.y << 3;
    const int col  = j0 + (jh << 5) + lane;
    const int k4b  = kc << 4;
    const int jc   = (jh << 5) + lane;

    const int gb = tid >> 6;
    const int gj = tid & 63;

    const float4* w0p = wpk + ((size_t)(0 * 128 + k4b) << 9) + col;
    const float4* w1p = wpk + ((size_t)(1 * 128 + k4b) << 9) + col;
    const float4* w2p = wpk + ((size_t)(2 * 128 + k4b) << 9) + col;

    for (int s = 0; s < S; s++) {
        if (s == 0) {
            for (int i = tid; i < 1024; i += 512) hs4[i] = make_float4(0.f, 0.f, 0.f, 0.f);
        } else {
            const float4* hp = (const float4*)(ys + ((size_t)(s - 1) * B_SZ + b0) * H_SZ);
            for (int i = tid; i < 1024; i += 512) hs4[i] = __ldcg(hp + i);
        }
        __syncthreads();

        float acc[3][8];
#pragma unroll
        for (int g = 0; g < 3; g++)
#pragma unroll
            for (int b = 0; b < 8; b++) acc[g][b] = 0.f;

#pragma unroll 4
        for (int t = 0; t < 16; t++) {
            float4 w0 = __ldg(w0p + ((size_t)t << 9));
            float4 w1 = __ldg(w1p + ((size_t)t << 9));
            float4 w2 = __ldg(w2p + ((size_t)t << 9));
            const int k4 = k4b + t;
#pragma unroll
            for (int b = 0; b < 8; b++) {
                float4 h4 = hs4[b * 128 + k4];
                acc[0][b] += h4.x * w0.x + h4.y * w0.y + h4.z * w0.z + h4.w * w0.w;
                acc[1][b] += h4.x * w1.x + h4.y * w1.y + h4.z * w1.z + h4.w * w1.w;
                acc[2][b] += h4.x * w2.x + h4.y * w2.y + h4.z * w2.z + h4.w * w2.w;
            }
        }

#pragma unroll
        for (int g = 0; g < 3; g++)
#pragma unroll
            for (int b = 0; b < 8; b++)
                red[((kc * 3 + g) * 8 + b) * 64 + jc] = acc[g][b];
        __syncthreads();

        float a0 = 0.f, a1 = 0.f, a2 = 0.f;
#pragma unroll
        for (int c = 0; c < 8; c++) {
            a0 += red[((c * 3 + 0) * 8 + gb) * 64 + gj];
            a1 += red[((c * 3 + 1) * 8 + gb) * 64 + gj];
            a2 += red[((c * 3 + 2) * 8 + gb) * 64 + gj];
        }

        float hprev = hs[gb * 512 + j0 + gj];

        const size_t xi = ((size_t)s * 3 * B_SZ + (b0 + gb)) * H_SZ + j0 + gj;
        float x0 = xg[xi];
        float x1 = xg[xi + (size_t)B_SZ * H_SZ];
        float x2 = xg[xi + (size_t)2 * B_SZ * H_SZ];

        float r  = 1.f / (1.f + expf(-(x0 + a0)));
        float z  = 1.f / (1.f + expf(-(x1 + a1)));
        float n  = tanhf(x2 + r * a2);
        float hn = (1.f - z) * n + z * hprev;

        ys[((size_t)s * B_SZ + b0 + gb) * H_SZ + j0 + gj] = hn;

        asm volatile("barrier.cluster.arrive.aligned;" ::: "memory");
        asm volatile("barrier.cluster.wait.aligned;"   ::: "memory");
    }
}

// ---------------- backward shortcut + final FC (unchanged) ----------------
__global__ void __launch_bounds__(128) bwd_step(
    const float* __restrict__ xin, long bstride, long off,
    const float* __restrict__ Wi, const float* __restrict__ bias,
    float* __restrict__ hout)
{
    int h = blockIdx.x * 128 + threadIdx.x;
    int b = blockIdx.y;
    const float* xr = xin + (size_t)b * bstride + off;
    const float* W1 = Wi + (size_t)1 * 512 * 512 + h;
    const float* W2 = Wi + (size_t)2 * 512 * 512 + h;
    float a1 = 0.f, a2 = 0.f;
    for (int k = 0; k < 512; k++) {
        float xv = __ldg(xr + k);
        a1 += xv * W1[(size_t)k * 512];
        a2 += xv * W2[(size_t)k * 512];
    }
    float z = 1.f / (1.f + expf(-(a1 + bias[512 + h])));
    float n = tanhf(a2 + bias[1024 + h]);
    hout[(size_t)b * 512 + h] = (1.f - z) * n;
}

__global__ void __launch_bounds__(128) fc_kernel(
    const float* __restrict__ ysl, const float* __restrict__ hb,
    const float* __restrict__ fw, const float* __restrict__ fb,
    float* __restrict__ out)
{
    int o = blockIdx.x * 128 + threadIdx.x;
    int b = blockIdx.y;
    float acc = fb[o];
    const float* f0 = ysl + (size_t)b * 512;
    const float* h0 = hb  + (size_t)b * 512;
    for (int jq = 0; jq < 512; jq++) acc += f0[jq] * fw[(size_t)jq * 512 + o];
    for (int jq = 0; jq < 512; jq++) acc += h0[jq] * fw[(size_t)(512 + jq) * 512 + o];
    out[(size_t)b * 512 + o] = acc;
}

// ---------------- launch ----------------
extern "C" void kernel_launch(void* const* d_in, const int* in_sizes, int n_in,
                              void* d_out, int out_size)
{
    (void)in_sizes; (void)n_in; (void)out_size;
    const float* x  = (const float*)d_in[0];
    const float* Wi = (const float*)d_in[1];
    const float* Wh = (const float*)d_in[2];
    const float* bb = (const float*)d_in[3];
    const float* fw = (const float*)d_in[4];
    const float* fb = (const float*)d_in[5];
    float* out = (float*)d_out;

    float *xg, *ys0, *ys1, *hb0, *hb1, *wpk0, *wpk1, *wf0, *wf1;
    cudaGetSymbolAddress((void**)&xg,   g_xg);
    cudaGetSymbolAddress((void**)&ys0,  g_ys0);
    cudaGetSymbolAddress((void**)&ys1,  g_ys1);
    cudaGetSymbolAddress((void**)&hb0,  g_hb0);
    cudaGetSymbolAddress((void**)&hb1,  g_hb1);
    cudaGetSymbolAddress((void**)&wpk0, g_wpk0);
    cudaGetSymbolAddress((void**)&wpk1, g_wpk1);
    cudaGetSymbolAddress((void**)&wf0,  g_wf0);
    cudaGetSymbolAddress((void**)&wf1,  g_wf1);

    cudaFuncSetAttribute(scan16t_kernel, cudaFuncAttributeMaxDynamicSharedMemorySize,
                         S16T_SMEM_BYTES);
    cudaFuncSetAttribute(scan16t_kernel, cudaFuncAttributeNonPortableClusterSizeAllowed, 1);
    cudaFuncSetAttribute(scan8_kernel, cudaFuncAttributeMaxDynamicSharedMemorySize,
                         SCAN8_SMEM_BYTES);

    int maxc = 0;
    {
        cudaLaunchConfig_t qcfg = {};
        qcfg.gridDim = dim3(16, 4);
        qcfg.blockDim = dim3(512);
        qcfg.dynamicSmemBytes = S16T_SMEM_BYTES;
        if (cudaOccupancyMaxPotentialClusterSize(&maxc, scan16t_kernel, &qcfg) != cudaSuccess)
            maxc = 0;
    }
    const bool use16 = (maxc >= 16);

    const size_t WSLAB = (size_t)3 * 512 * 512;
    const size_t BSLAB = (size_t)3 * 512;
    const size_t YSSTEP = (size_t)B_SZ * H_SZ;

    dim3 pgrid(12, 512);
    int  pkblocks = (3 * 512 * 512 + 255) / 256;

    if (use16) {
        pack_frag<<<(FRAG_PAIRS + 255) / 256, 256>>>(Wh + 0 * WSLAB, wf0);
        pack_frag<<<(FRAG_PAIRS + 255) / 256, 256>>>(Wh + 2 * WSLAB, wf1);
    } else {
        pack_wh<<<pkblocks, 256>>>(Wh + 0 * WSLAB, wpk0);
        pack_wh<<<pkblocks, 256>>>(Wh + 2 * WSLAB, wpk1);
    }

    auto launch_scan = [&](const float* xgp, const float* wfp, const float* wpkp, float* ysp) {
        if (use16) {
            cudaLaunchConfig_t cfg = {};
            cfg.gridDim = dim3(16, 4);
            cfg.blockDim = dim3(512);
            cfg.dynamicSmemBytes = S16T_SMEM_BYTES;
            cfg.stream = 0;
            cudaLaunchAttribute at[1];
            at[0].id = cudaLaunchAttributeClusterDimension;
            at[0].val.clusterDim.x = 16;
            at[0].val.clusterDim.y = 1;
            at[0].val.clusterDim.z = 1;
            cfg.attrs = at;
            cfg.numAttrs = 1;
            int S = S_SZ;
            cudaLaunchKernelEx(&cfg, scan16t_kernel, xgp, wfp, ysp, S);
        } else {
            scan8_kernel<<<dim3(8, 8), 512, SCAN8_SMEM_BYTES>>>(
                xgp, (const float4*)wpkp, ysp, S_SZ);
        }
    };

    proj_kernel<<<pgrid, 256>>>(x, (long)S_SZ * I_SZ, (long)I_SZ,
                                Wi + 0 * WSLAB, bb + 0 * BSLAB, xg, S_SZ);
    launch_scan(xg, wf0, wpk0, ys0);

    proj_kernel<<<pgrid, 256>>>(ys0, (long)H_SZ, (long)B_SZ * H_SZ,
                                Wi + 2 * WSLAB, bb + 2 * BSLAB, xg, S_SZ);
    launch_scan(xg, wf1, wpk1, ys1);

    dim3 bgrid(4, 64);
    bwd_step<<<bgrid, 128>>>(x, (long)S_SZ * I_SZ, (long)(S_SZ - 1) * I_SZ,
                             Wi + 1 * WSLAB, bb + 1 * BSLAB, hb0);
    bwd_step<<<bgrid, 128>>>(hb0, (long)H_SZ, 0L,
                             Wi + 3 * WSLAB, bb + 3 * BSLAB, hb1);

    fc_kernel<<<bgrid, 128>>>(ys1 + (size_t)(S_SZ - 1) * YSSTEP, hb1, fw, fb, out);
}

// round 15
// speedup vs baseline: 2.1892x; 2.1892x over previous
#include <cuda_runtime.h>
#include <cuda_fp16.h>
#include <math.h>

#define B_SZ 64
#define S_SZ 1024
#define I_SZ 512
#define H_SZ 512

// ---------------- static device scratch (no allocations allowed) ----------------
__device__ float  g_xg  [(size_t)S_SZ * 3 * B_SZ * H_SZ];  // [S][3][B][H]
__device__ float  g_ys0 [(size_t)S_SZ * B_SZ * H_SZ];      // layer-0 fwd outputs (exact fp32)
__device__ float  g_ys1 [(size_t)S_SZ * B_SZ * H_SZ];      // layer-1 fwd outputs
__device__ __half g_yh  [(size_t)S_SZ * B_SZ * H_SZ];      // fp16 mirror of current layer's h
__device__ float  g_hb0 [B_SZ * H_SZ];
__device__ float  g_hb1 [B_SZ * H_SZ];
__device__ float  g_wpk0[3 * 512 * 512];                   // packed Wh layer0 (fallback path)
__device__ float  g_wpk1[3 * 512 * 512];                   // packed Wh layer1 (fallback path)
__device__ unsigned long long g_wf0[196608];               // fp16 frag-packed Wh layer0
__device__ unsigned long long g_wf1[196608];               // fp16 frag-packed Wh layer1

// ---------------- helpers ----------------
__device__ __forceinline__ unsigned f2tf(float x) {
    unsigned u;
    asm("cvt.rna.tf32.f32 %0, %1;" : "=r"(u) : "f"(x));
    return u;
}

__device__ __forceinline__ void mma8(float* c, const unsigned* a, unsigned b0, unsigned b1) {
    asm volatile(
        "mma.sync.aligned.m16n8k8.row.col.f32.tf32.tf32.f32 "
        "{%0,%1,%2,%3}, {%4,%5,%6,%7}, {%8,%9}, {%0,%1,%2,%3};"
        : "+f"(c[0]), "+f"(c[1]), "+f"(c[2]), "+f"(c[3])
        : "r"(a[0]), "r"(a[1]), "r"(a[2]), "r"(a[3]), "r"(b0), "r"(b1));
}

__device__ __forceinline__ void mma16(float* c, const unsigned* a, unsigned b0, unsigned b1) {
    asm volatile(
        "mma.sync.aligned.m16n8k16.row.col.f32.f16.f16.f32 "
        "{%0,%1,%2,%3}, {%4,%5,%6,%7}, {%8,%9}, {%0,%1,%2,%3};"
        : "+f"(c[0]), "+f"(c[1]), "+f"(c[2]), "+f"(c[3])
        : "r"(a[0]), "r"(a[1]), "r"(a[2]), "r"(a[3]), "r"(b0), "r"(b1));
}

// ---------------- projection GEMM (round-13 verified, pipelined) ----------------
__global__ void __launch_bounds__(256) proj_kernel(
    const float* __restrict__ X, long sb, long ss,
    const float* __restrict__ W, const float* __restrict__ bias,
    float* __restrict__ out, int Srows)
{
    __shared__ float As[128][36];
    __shared__ float Bs[32][136];

    const int M  = Srows * B_SZ;
    const int m0 = blockIdx.y * 128;
    const int n0 = blockIdx.x * 128;
    const int g  = n0 >> 9;
    const int h0 = n0 & 511;
    const float* Wg = W + (size_t)g * H_SZ * H_SZ;

    const int tid  = threadIdx.x;
    const int lane = tid & 31;
    const int warp = tid >> 5;
    const int wm   = warp & 3;
    const int wn   = warp >> 2;

    float acc[2][8][4];
#pragma unroll
    for (int i = 0; i < 2; i++)
#pragma unroll
        for (int jf = 0; jf < 8; jf++)
#pragma unroll
            for (int k = 0; k < 4; k++) acc[i][jf][k] = 0.f;

    float4 av[4], bv[4];

#pragma unroll
    for (int i = 0; i < 4; i++) {
        int idx = tid + i * 256;
        int row = idx >> 3;
        int kk  = (idx & 7) << 2;
        av[i] = make_float4(0.f, 0.f, 0.f, 0.f);
        int r = m0 + row;
        if (r < M) {
            int s = r >> 6, b = r & 63;
            av[i] = *(const float4*)(X + (size_t)b * sb + (size_t)s * ss + kk);
        }
        int kkb = idx >> 5;
        int nn  = (idx & 31) << 2;
        bv[i] = *(const float4*)(Wg + (size_t)kkb * H_SZ + h0 + nn);
    }

    for (int k0 = 0; k0 < H_SZ; k0 += 32) {
#pragma unroll
        for (int i = 0; i < 4; i++) {
            int idx = tid + i * 256;
            int row = idx >> 3;
            int kk  = (idx & 7) << 2;
            As[row][kk + 0] = __uint_as_float(f2tf(av[i].x));
            As[row][kk + 1] = __uint_as_float(f2tf(av[i].y));
            As[row][kk + 2] = __uint_as_float(f2tf(av[i].z));
            As[row][kk + 3] = __uint_as_float(f2tf(av[i].w));
            int kkb = idx >> 5;
            int nn  = (idx & 31) << 2;
            Bs[kkb][nn + 0] = __uint_as_float(f2tf(bv[i].x));
            Bs[kkb][nn + 1] = __uint_as_float(f2tf(bv[i].y));
            Bs[kkb][nn + 2] = __uint_as_float(f2tf(bv[i].z));
            Bs[kkb][nn + 3] = __uint_as_float(f2tf(bv[i].w));
        }
        __syncthreads();

        if (k0 + 32 < H_SZ) {
            const int kn = k0 + 32;
#pragma unroll
            for (int i = 0; i < 4; i++) {
                int idx = tid + i * 256;
                int row = idx >> 3;
                int kk  = (idx & 7) << 2;
                av[i] = make_float4(0.f, 0.f, 0.f, 0.f);
                int r = m0 + row;
                if (r < M) {
                    int s = r >> 6, b = r & 63;
                    av[i] = *(const float4*)(X + (size_t)b * sb + (size_t)s * ss + kn + kk);
                }
                int kkb = idx >> 5;
                int nn  = (idx & 31) << 2;
                bv[i] = *(const float4*)(Wg + (size_t)(kn + kkb) * H_SZ + h0 + nn);
            }
        }

#pragma unroll
        for (int kq = 0; kq < 4; kq++) {
            const int kr = kq * 8;
            unsigned a[2][4];
#pragma unroll
            for (int mf = 0; mf < 2; mf++) {
                int rb = wm * 32 + mf * 16 + (lane >> 2);
                int c  = kr + (lane & 3);
                a[mf][0] = __float_as_uint(As[rb][c]);
                a[mf][1] = __float_as_uint(As[rb + 8][c]);
                a[mf][2] = __float_as_uint(As[rb][c + 4]);
                a[mf][3] = __float_as_uint(As[rb + 8][c + 4]);
            }
#pragma unroll
            for (int nf = 0; nf < 8; nf++) {
                int cb = wn * 64 + nf * 8 + (lane >> 2);
                unsigned b0 = __float_as_uint(Bs[kr + (lane & 3)][cb]);
                unsigned b1 = __float_as_uint(Bs[kr + (lane & 3) + 4][cb]);
                mma8(acc[0][nf], a[0], b0, b1);
                mma8(acc[1][nf], a[1], b0, b1);
            }
        }
        __syncthreads();
    }

#pragma unroll
    for (int mf = 0; mf < 2; mf++) {
#pragma unroll
        for (int nf = 0; nf < 8; nf++) {
            int col = wn * 64 + nf * 8 + ((lane & 3) << 1);
            int h   = h0 + col;
            float b0v = bias[g * H_SZ + h];
            float b1v = bias[g * H_SZ + h + 1];
            int r = m0 + wm * 32 + mf * 16 + (lane >> 2);
            if (r < M) {
                int s = r >> 6, b = r & 63;
                float* o = out + ((size_t)(s * 3 + g) * B_SZ + b) * H_SZ + h;
                o[0] = acc[mf][nf][0] + b0v;
                o[1] = acc[mf][nf][1] + b1v;
            }
            int r2 = r + 8;
            if (r2 < M) {
                int s = r2 >> 6, b = r2 & 63;
                float* o = out + ((size_t)(s * 3 + g) * B_SZ + b) * H_SZ + h;
                o[0] = acc[mf][nf][2] + b0v;
                o[1] = acc[mf][nf][3] + b1v;
            }
        }
    }
}

// ---------------- Wh pre-pack for fallback scan8 ----------------
__global__ void __launch_bounds__(256) pack_wh(const float* __restrict__ Wh,
                                               float* __restrict__ wpk)
{
    int idx = blockIdx.x * 256 + threadIdx.x;
    if (idx < 3 * 512 * 512) {
        int col = idx & 511;
        int k   = (idx >> 9) & 511;
        int g   = idx >> 18;
        wpk[((((size_t)g * 128 + (k >> 2)) * 512 + col) << 2) + (k & 3)] = Wh[idx];
    }
}

// ---------------- Wh fp16 frag-pack for tensor scan ----------------
// p = (((g*16 + cg)*4 + nf)*32 + kt)*32 + lane ; k0 = kt*16 + (lane&3)*2 ;
// col = cg*32 + nf*8 + (lane>>2)
// lo b32 = half2(W[k0][col],   W[k0+1][col])   (B-frag b0)
// hi b32 = half2(W[k0+8][col], W[k0+9][col])   (B-frag b1)
#define FRAG16_N 196608
__global__ void __launch_bounds__(256) pack_frag16(const float* __restrict__ Wh,
                                                   unsigned long long* __restrict__ wf)
{
    int p = blockIdx.x * 256 + threadIdx.x;
    if (p < FRAG16_N) {
        int lane = p & 31;
        int kt   = (p >> 5) & 31;
        int nf   = (p >> 10) & 3;
        int cg   = (p >> 12) & 15;
        int g    = p >> 16;
        int col  = cg * 32 + nf * 8 + (lane >> 2);
        int k0   = kt * 16 + ((lane & 3) << 1);
        __half2 lo = __floats2half2_rn(Wh[((size_t)g * 512 + k0)     * 512 + col],
                                       Wh[((size_t)g * 512 + k0 + 1) * 512 + col]);
        __half2 hi = __floats2half2_rn(Wh[((size_t)g * 512 + k0 + 8) * 512 + col],
                                       Wh[((size_t)g * 512 + k0 + 9) * 512 + col]);
        unsigned lou = *(unsigned*)&lo;
        unsigned hiu = *(unsigned*)&hi;
        wf[p] = (unsigned long long)lou | ((unsigned long long)hiu << 32);
    }
}

// ================= PRIMARY scan: fp16 tensor mma, cluster-16 =================
// grid (16, 4): x = colgroup (32 cols), y = bgrp (16 batches). Cluster 16 along x.
// Warps 0-11 mma (kc = w&3 K-slice of 128, g = w>>2 gate). ALL 3 gates' fp16 weights
// in smem (96 KB). h staged from fp16 mirror yh; ys keeps exact fp32 h for downstream.
#define HS2 520                                    // halves per hs row (512 + 8 pad)
#define SM_HS_F   24576                            // float offset of hs (after 96 KB weights)
#define SM_RED_F  (24576 + 16 * HS2 / 2)           // 28736
#define S16_SMEM_BYTES ((SM_RED_F + 4 * 16 * 100) * 4)   // 140544 B

__global__ void __launch_bounds__(512, 1)
scan16t_kernel(const float* __restrict__ xg,            // [S][3][B][H]
               const unsigned long long* __restrict__ wf, // fp16 frag-packed Wh
               float* __restrict__ ys,                  // [S][B][H] exact fp32 h
               __half* __restrict__ yh,                 // [S][B][H] fp16 mirror
               int S)
{
    extern __shared__ float sm[];
    unsigned long long* wsm = (unsigned long long*)sm;  // [3][4 nf][32 kt][32 lane]
    __half*             hsm = (__half*)(sm + SM_HS_F);  // [16][HS2]
    float*              red = sm + SM_RED_F;            // [4 kc][16 row][100]

    const int tid  = threadIdx.x;
    const int lane = tid & 31;
    const int w    = tid >> 5;
    const int kc   = w & 3;
    const int g    = w >> 2;
    const int cg   = blockIdx.x;
    const int j0   = cg << 5;
    const int b0   = blockIdx.y << 4;

    // one-time: copy all 3 gates' frag slices for this cg (each 4096 ull contiguous)
    {
        const uint4* src = (const uint4*)wf;
        uint4*       dst = (uint4*)wsm;
#pragma unroll
        for (int gg = 0; gg < 3; gg++) {
            const uint4* s4 = src + (size_t)(gg * 16 + cg) * 2048;
            uint4*       d4 = dst + gg * 2048;
            for (int i = tid; i < 2048; i += 512) d4[i] = s4[i];
        }
    }

    const int gb = tid >> 5;   // gate-stage batch (0..15)
    const int gj = tid & 31;   // gate-stage col   (0..31)

    const int rb = lane >> 2;
    const int q2 = (lane & 3) << 1;

    float hprev = 0.f;

    float x0, x1, x2;
    {
        const size_t xb = ((size_t)(0 * 3 + 0) * B_SZ + b0 + gb) * H_SZ + j0 + gj;
        x0 = __ldg(xg + xb);
        x1 = __ldg(xg + xb + (size_t)B_SZ * H_SZ);
        x2 = __ldg(xg + xb + (size_t)2 * B_SZ * H_SZ);
    }

    for (int s = 0; s < S; s++) {
        // stage h_prev [16][512] fp16 (coalesced uint4 = 8 halves)
        if (s == 0) {
            uint4 z = make_uint4(0u, 0u, 0u, 0u);
            for (int i = tid; i < 16 * (HS2 / 8); i += 512)   // 1040 uint4 incl. pads
                ((uint4*)hsm)[i] = z;
        } else {
            const __half* yp = yh + (size_t)(s - 1) * (B_SZ * H_SZ);
#pragma unroll
            for (int it = 0; it < 2; it++) {
                int i  = tid + it * 512;    // 0..1023
                int b  = i >> 6;
                int c4 = i & 63;
                uint4 v = __ldcg((const uint4*)(yp + (size_t)(b0 + b) * H_SZ) + c4);
                *((uint4*)(hsm + b * HS2) + c4) = v;
            }
        }
        __syncthreads();

        // fp16 tensor matvec (warps 0-11): per warp 8 kt-chunks x 4 nf = 32 mma
        if (w < 12) {
            const int ktb = kc << 3;
            const __half* hr0 = hsm + rb * HS2;
            const __half* hr1 = hsm + (rb + 8) * HS2;
            const unsigned long long* wg = wsm + g * 4096 + lane;

            float c[4][4];
#pragma unroll
            for (int nf = 0; nf < 4; nf++)
#pragma unroll
                for (int q = 0; q < 4; q++) c[nf][q] = 0.f;

#pragma unroll
            for (int t = 0; t < 8; t++) {
                const int kt = ktb + t;
                const int kb = (kt << 4) + q2;
                unsigned a[4];
                a[0] = *(const unsigned*)(hr0 + kb);
                a[1] = *(const unsigned*)(hr1 + kb);
                a[2] = *(const unsigned*)(hr0 + kb + 8);
                a[3] = *(const unsigned*)(hr1 + kb + 8);
#pragma unroll
                for (int nf = 0; nf < 4; nf++) {
                    unsigned long long bv = wg[((nf << 5) + kt) << 5];
                    mma16(c[nf], a, (unsigned)bv, (unsigned)(bv >> 32));
                }
            }

#pragma unroll
            for (int nf = 0; nf < 4; nf++) {
                int gcol = (g << 5) + (nf << 3) + ((lane & 3) << 1);
                int row  = lane >> 2;
                float2 p01 = make_float2(c[nf][0], c[nf][1]);
                float2 p23 = make_float2(c[nf][2], c[nf][3]);
                *(float2*)&red[kc * 1600 + row * 100 + gcol]       = p01;
                *(float2*)&red[kc * 1600 + (row + 8) * 100 + gcol] = p23;
            }
        }
        __syncthreads();

        // gate stage: 512 threads, one per (batch gb, col gj)
        {
            float s0 = 0.f, s1 = 0.f, s2 = 0.f;
#pragma unroll
            for (int c8 = 0; c8 < 4; c8++) {
                s0 += red[c8 * 1600 + gb * 100 +      gj];
                s1 += red[c8 * 1600 + gb * 100 + 32 + gj];
                s2 += red[c8 * 1600 + gb * 100 + 64 + gj];
            }
            float r  = 1.f / (1.f + expf(-(x0 + s0)));
            float z  = 1.f / (1.f + expf(-(x1 + s1)));
            float n  = tanhf(x2 + r * s2);
            float hn = (1.f - z) * n + z * hprev;
            hprev = hn;
            const size_t oi = ((size_t)s * B_SZ + b0 + gb) * H_SZ + j0 + gj;
            ys[oi] = hn;                         // exact fp32 for downstream
            yh[oi] = __float2half_rn(hn);        // fp16 for next-step mma
        }

        // split cluster barrier; prefetch next xg in the gap
        asm volatile("barrier.cluster.arrive.aligned;" ::: "memory");
        if (s + 1 < S) {
            const size_t xb = ((size_t)((s + 1) * 3 + 0) * B_SZ + b0 + gb) * H_SZ + j0 + gj;
            x0 = __ldg(xg + xb);
            x1 = __ldg(xg + xb + (size_t)B_SZ * H_SZ);
            x2 = __ldg(xg + xb + (size_t)2 * B_SZ * H_SZ);
        }
        asm volatile("barrier.cluster.wait.aligned;" ::: "memory");
    }
}

// ================= FALLBACK scan: exact round-6 kernel (cluster 8) =================
#define SCAN8_SMEM_BYTES ((4096 + 12288) * 4)

__global__ void __launch_bounds__(512, 1) __cluster_dims__(8, 1, 1)
scan8_kernel(const float* __restrict__ xg, const float4* __restrict__ wpk,
             float* __restrict__ ys, int S)
{
    extern __shared__ float sm[];
    float*  hs  = sm;
    float*  red = sm + 4096;
    float4* hs4 = (float4*)hs;

    const int tid  = threadIdx.x;
    const int lane = tid & 31;
    const int w    = tid >> 5;
    const int kc   = w >> 1;
    const int jh   = w & 1;
    const int j0   = blockIdx.x << 6;
    const int b0   = blockIdx.y << 3;
    const int col  = j0 + (jh << 5) + lane;
    const int k4b  = kc << 4;
    const int jc   = (jh << 5) + lane;

    const int gb = tid >> 6;
    const int gj = tid & 63;

    const float4* w0p = wpk + ((size_t)(0 * 128 + k4b) << 9) + col;
    const float4* w1p = wpk + ((size_t)(1 * 128 + k4b) << 9) + col;
    const float4* w2p = wpk + ((size_t)(2 * 128 + k4b) << 9) + col;

    for (int s = 0; s < S; s++) {
        if (s == 0) {
            for (int i = tid; i < 1024; i += 512) hs4[i] = make_float4(0.f, 0.f, 0.f, 0.f);
        } else {
            const float4* hp = (const float4*)(ys + ((size_t)(s - 1) * B_SZ + b0) * H_SZ);
            for (int i = tid; i < 1024; i += 512) hs4[i] = __ldcg(hp + i);
        }
        __syncthreads();

        float acc[3][8];
#pragma unroll
        for (int g = 0; g < 3; g++)
#pragma unroll
            for (int b = 0; b < 8; b++) acc[g][b] = 0.f;

#pragma unroll 4
        for (int t = 0; t < 16; t++) {
            float4 w0 = __ldg(w0p + ((size_t)t << 9));
            float4 w1 = __ldg(w1p + ((size_t)t << 9));
            float4 w2 = __ldg(w2p + ((size_t)t << 9));
            const int k4 = k4b + t;
#pragma unroll
            for (int b = 0; b < 8; b++) {
                float4 h4 = hs4[b * 128 + k4];
                acc[0][b] += h4.x * w0.x + h4.y * w0.y + h4.z * w0.z + h4.w * w0.w;
                acc[1][b] += h4.x * w1.x + h4.y * w1.y + h4.z * w1.z + h4.w * w1.w;
                acc[2][b] += h4.x * w2.x + h4.y * w2.y + h4.z * w2.z + h4.w * w2.w;
            }
        }

#pragma unroll
        for (int g = 0; g < 3; g++)
#pragma unroll
            for (int b = 0; b < 8; b++)
                red[((kc * 3 + g) * 8 + b) * 64 + jc] = acc[g][b];
        __syncthreads();

        float a0 = 0.f, a1 = 0.f, a2 = 0.f;
#pragma unroll
        for (int c = 0; c < 8; c++) {
            a0 += red[((c * 3 + 0) * 8 + gb) * 64 + gj];
            a1 += red[((c * 3 + 1) * 8 + gb) * 64 + gj];
            a2 += red[((c * 3 + 2) * 8 + gb) * 64 + gj];
        }

        float hprev = hs[gb * 512 + j0 + gj];

        const size_t xi = ((size_t)s * 3 * B_SZ + (b0 + gb)) * H_SZ + j0 + gj;
        float x0 = xg[xi];
        float x1 = xg[xi + (size_t)B_SZ * H_SZ];
        float x2 = xg[xi + (size_t)2 * B_SZ * H_SZ];

        float r  = 1.f / (1.f + expf(-(x0 + a0)));
        float z  = 1.f / (1.f + expf(-(x1 + a1)));
        float n  = tanhf(x2 + r * a2);
        float hn = (1.f - z) * n + z * hprev;

        ys[((size_t)s * B_SZ + b0 + gb) * H_SZ + j0 + gj] = hn;

        asm volatile("barrier.cluster.arrive.aligned;" ::: "memory");
        asm volatile("barrier.cluster.wait.aligned;"   ::: "memory");
    }
}

// ---------------- backward shortcut + final FC (unchanged) ----------------
__global__ void __launch_bounds__(128) bwd_step(
    const float* __restrict__ xin, long bstride, long off,
    const float* __restrict__ Wi, const float* __restrict__ bias,
    float* __restrict__ hout)
{
    int h = blockIdx.x * 128 + threadIdx.x;
    int b = blockIdx.y;
    const float* xr = xin + (size_t)b * bstride + off;
    const float* W1 = Wi + (size_t)1 * 512 * 512 + h;
    const float* W2 = Wi + (size_t)2 * 512 * 512 + h;
    float a1 = 0.f, a2 = 0.f;
    for (int k = 0; k < 512; k++) {
        float xv = __ldg(xr + k);
        a1 += xv * W1[(size_t)k * 512];
        a2 += xv * W2[(size_t)k * 512];
    }
    float z = 1.f / (1.f + expf(-(a1 + bias[512 + h])));
    float n = tanhf(a2 + bias[1024 + h]);
    hout[(size_t)b * 512 + h] = (1.f - z) * n;
}

__global__ void __launch_bounds__(128) fc_kernel(
    const float* __restrict__ ysl, const float* __restrict__ hb,
    const float* __restrict__ fw, const float* __restrict__ fb,
    float* __restrict__ out)
{
    int o = blockIdx.x * 128 + threadIdx.x;
    int b = blockIdx.y;
    float acc = fb[o];
    const float* f0 = ysl + (size_t)b * 512;
    const float* h0 = hb  + (size_t)b * 512;
    for (int jq = 0; jq < 512; jq++) acc += f0[jq] * fw[(size_t)jq * 512 + o];
    for (int jq = 0; jq < 512; jq++) acc += h0[jq] * fw[(size_t)(512 + jq) * 512 + o];
    out[(size_t)b * 512 + o] = acc;
}

// ---------------- launch ----------------
extern "C" void kernel_launch(void* const* d_in, const int* in_sizes, int n_in,
                              void* d_out, int out_size)
{
    (void)in_sizes; (void)n_in; (void)out_size;
    const float* x  = (const float*)d_in[0];
    const float* Wi = (const float*)d_in[1];
    const float* Wh = (const float*)d_in[2];
    const float* bb = (const float*)d_in[3];
    const float* fw = (const float*)d_in[4];
    const float* fb = (const float*)d_in[5];
    float* out = (float*)d_out;

    float *xg, *ys0, *ys1, *hb0, *hb1, *wpk0, *wpk1;
    __half* yh;
    unsigned long long *wf0, *wf1;
    cudaGetSymbolAddress((void**)&xg,   g_xg);
    cudaGetSymbolAddress((void**)&ys0,  g_ys0);
    cudaGetSymbolAddress((void**)&ys1,  g_ys1);
    cudaGetSymbolAddress((void**)&yh,   g_yh);
    cudaGetSymbolAddress((void**)&hb0,  g_hb0);
    cudaGetSymbolAddress((void**)&hb1,  g_hb1);
    cudaGetSymbolAddress((void**)&wpk0, g_wpk0);
    cudaGetSymbolAddress((void**)&wpk1, g_wpk1);
    cudaGetSymbolAddress((void**)&wf0,  g_wf0);
    cudaGetSymbolAddress((void**)&wf1,  g_wf1);

    cudaFuncSetAttribute(scan16t_kernel, cudaFuncAttributeMaxDynamicSharedMemorySize,
                         S16_SMEM_BYTES);
    cudaFuncSetAttribute(scan16t_kernel, cudaFuncAttributeNonPortableClusterSizeAllowed, 1);
    cudaFuncSetAttribute(scan8_kernel, cudaFuncAttributeMaxDynamicSharedMemorySize,
                         SCAN8_SMEM_BYTES);

    int maxc = 0;
    {
        cudaLaunchConfig_t qcfg = {};
        qcfg.gridDim = dim3(16, 4);
        qcfg.blockDim = dim3(512);
        qcfg.dynamicSmemBytes = S16_SMEM_BYTES;
        if (cudaOccupancyMaxPotentialClusterSize(&maxc, scan16t_kernel, &qcfg) != cudaSuccess)
            maxc = 0;
    }
    const bool use16 = (maxc >= 16);

    const size_t WSLAB = (size_t)3 * 512 * 512;
    const size_t BSLAB = (size_t)3 * 512;
    const size_t YSSTEP = (size_t)B_SZ * H_SZ;

    dim3 pgrid(12, 512);
    int  pkblocks = (3 * 512 * 512 + 255) / 256;

    if (use16) {
        pack_frag16<<<(FRAG16_N + 255) / 256, 256>>>(Wh + 0 * WSLAB, wf0);
        pack_frag16<<<(FRAG16_N + 255) / 256, 256>>>(Wh + 2 * WSLAB, wf1);
    } else {
        pack_wh<<<pkblocks, 256>>>(Wh + 0 * WSLAB, wpk0);
        pack_wh<<<pkblocks, 256>>>(Wh + 2 * WSLAB, wpk1);
    }

    auto launch_scan = [&](const float* xgp, const unsigned long long* wfp,
                           const float* wpkp, float* ysp) {
        if (use16) {
            cudaLaunchConfig_t cfg = {};
            cfg.gridDim = dim3(16, 4);
            cfg.blockDim = dim3(512);
            cfg.dynamicSmemBytes = S16_SMEM_BYTES;
            cfg.stream = 0;
            cudaLaunchAttribute at[1];
            at[0].id = cudaLaunchAttributeClusterDimension;
            at[0].val.clusterDim.x = 16;
            at[0].val.clusterDim.y = 1;
            at[0].val.clusterDim.z = 1;
            cfg.attrs = at;
            cfg.numAttrs = 1;
            int S = S_SZ;
            cudaLaunchKernelEx(&cfg, scan16t_kernel, xgp, wfp, ysp, yh, S);
        } else {
            scan8_kernel<<<dim3(8, 8), 512, SCAN8_SMEM_BYTES>>>(
                xgp, (const float4*)wpkp, ysp, S_SZ);
        }
    };

    proj_kernel<<<pgrid, 256>>>(x, (long)S_SZ * I_SZ, (long)I_SZ,
                                Wi + 0 * WSLAB, bb + 0 * BSLAB, xg, S_SZ);
    launch_scan(xg, wf0, wpk0, ys0);

    proj_kernel<<<pgrid, 256>>>(ys0, (long)H_SZ, (long)B_SZ * H_SZ,
                                Wi + 2 * WSLAB, bb + 2 * BSLAB, xg, S_SZ);
    launch_scan(xg, wf1, wpk1, ys1);

    dim3 bgrid(4, 64);
    bwd_step<<<bgrid, 128>>>(x, (long)S_SZ * I_SZ, (long)(S_SZ - 1) * I_SZ,
                             Wi + 1 * WSLAB, bb + 1 * BSLAB, hb0);
    bwd_step<<<bgrid, 128>>>(hb0, (long)H_SZ, 0L,
                             Wi + 3 * WSLAB, bb + 3 * BSLAB, hb1);

    fc_kernel<<<bgrid, 128>>>(ys1 + (size_t)(S_SZ - 1) * YSSTEP, hb1, fw, fb, out);
}